// round 13
// baseline (speedup 1.0000x reference)
#include <cuda_runtime.h>
#include <cuda_fp16.h>
#include <cstdint>

#define NV 10000
#define NC 100000
#define B  256
#define GRID_MAIN 1184               // 148 SMs * 8 blocks
#define NWARPS (GRID_MAIN * 4)       // 4736 warps
#define CPW 22                       // ceil(NC / NWARPS) -> 11 pairs per warp
#define GRID_PREP 2048
#define GRID_SCAT 160

// Dual table: row 2v = x, row 2v+1 = 1-x; each row 128 half2 = 512 B.
// 10.24 MB, L2-resident; rel err per value <= 2^-11.
__device__ __align__(16) __half2 g_tab[2 * NV * (B / 2)];
// Clauses sorted by literal-0 variable: uint4 {w0,w1,w2,0}, w = v*256 + n*128
// (= half2 offset of the literal's table row). 1.6 MB.
__device__ __align__(16) uint4 g_cl[NC];
// v0 histogram + scatter cursors. Zero at load; re-zeroed by cnf_k each launch.
__device__ unsigned int g_cnt[NV];
__device__ unsigned int g_cur[NV];

__device__ __forceinline__ int probe_is64(const unsigned int* __restrict__ idx_raw,
                                          int tid, int* s_flag) {
    // int64 data (small non-negative) -> odd 32-bit words all 0;
    // int32 data -> odd words are random indices, all-zero ~impossible.
    if (tid < 32) {
        unsigned int acc = 0;
        #pragma unroll
        for (int k = 0; k < 4; ++k) acc |= idx_raw[2 * (tid + 32 * k) + 1];
        acc = __reduce_or_sync(0xFFFFFFFFu, acc);
        if (tid == 0) *s_flag = (acc == 0) ? 1 : 0;
    }
    __syncthreads();
    return *s_flag;
}

// Node 1: dtype detect, v0 histogram, fp16 dual table build, init d_out.
__global__ void __launch_bounds__(256)
prep_k(const float* __restrict__ input,
       const unsigned int* __restrict__ idx_raw,
       unsigned int* __restrict__ out) {
    __shared__ int s_is64;
    const int tid = threadIdx.x;
    const int stride = probe_is64(idx_raw, tid, &s_is64) ? 2 : 1;

    const int gtid = blockIdx.x * 256 + tid;
    const int gsz  = GRID_PREP * 256;

    if (gtid < B) out[gtid] = 0x7F800000u;   // +inf (d_out poisoned each replay)

    // histogram of literal-0 variable per clause
    for (int c = gtid; c < NC; c += gsz) {
        unsigned int v = idx_raw[(c * 3) * stride];
        if (v >= NV) v = NV - 1;
        atomicAdd(&g_cnt[v], 1u);
    }

    // dual table; 1-x computed in fp32 (exact), rounded once to fp16
    for (int i = gtid; i < NV * (B / 2); i += gsz) {
        int v = i >> 7;
        int j = i & 127;
        float2 x = ((const float2*)input)[i];
        g_tab[v * 256 + j]       = __floats2half2_rn(x.x, x.y);
        g_tab[v * 256 + 128 + j] = __floats2half2_rn(1.0f - x.x, 1.0f - x.y);
    }
}

// Node 2: every block redundantly computes the exclusive scan of g_cnt in
// SMEM (no extra kernel / no grid sync needed), then scatters its clause
// slice into g_cl at base[v0] + atomicAdd(g_cur[v0]). Order within a bucket
// is nondeterministic; the min-reduction is order-invariant, so the output
// is bit-identical regardless.
__global__ void __launch_bounds__(256)
scatter_k(const unsigned int* __restrict__ idx_raw,
          const unsigned int* __restrict__ neg_raw) {
    __shared__ int s_is64;
    __shared__ unsigned int s_base[NV];     // 40 KB
    __shared__ unsigned int s_tot[256];

    const int tid = threadIdx.x;
    const int stride = probe_is64(idx_raw, tid, &s_is64) ? 2 : 1;

    // per-thread chunk of 40 counts (256*40 = 10240 >= NV)
    const int v0c = tid * 40;
    unsigned int loc[40];
    unsigned int tot = 0;
    #pragma unroll
    for (int k = 0; k < 40; ++k) {
        int v = v0c + k;
        unsigned int c = (v < NV) ? g_cnt[v] : 0u;
        loc[k] = tot;           // local exclusive prefix
        tot += c;
    }
    s_tot[tid] = tot;
    __syncthreads();
    // block inclusive scan (Hillis-Steele)
    for (int off = 1; off < 256; off <<= 1) {
        unsigned int v = (tid >= off) ? s_tot[tid - off] : 0u;
        __syncthreads();
        s_tot[tid] += v;
        __syncthreads();
    }
    unsigned int excl = s_tot[tid] - tot;
    #pragma unroll
    for (int k = 0; k < 40; ++k) {
        int v = v0c + k;
        if (v < NV) s_base[v] = excl + loc[k];
    }
    __syncthreads();

    const int gtid = blockIdx.x * 256 + tid;
    const int gsz  = GRID_SCAT * 256;
    for (int c = gtid; c < NC; c += gsz) {
        unsigned int w[3];
        #pragma unroll
        for (int s = 0; s < 3; ++s) {
            unsigned int v = idx_raw[(c * 3 + s) * stride];
            unsigned int n = neg_raw[(c * 3 + s) * stride] & 1u;
            if (v >= NV) v = NV - 1;
            w[s] = v * 256u + n * 128u;
        }
        unsigned int v0 = w[0] >> 8;
        unsigned int pos = s_base[v0] + atomicAdd(&g_cur[v0], 1u);
        g_cl[pos] = make_uint4(w[0], w[1], w[2], 0u);
    }
}

__device__ __forceinline__ __half2 h2(unsigned int u) {
    return *reinterpret_cast<__half2*>(&u);
}

// Node 3: R11's warp-per-row gather engine, but each warp processes a
// CONTIGUOUS run of sorted clauses -> its ~22 literal-0 rows collapse to
// ~2-3 distinct rows (L1/L1tex-coalesced), cutting L2 slice-requests.
// One LDG.128 per 512B row; clause max entirely in-lane; 2 clauses/iter.
// Clamped clause indices: duplicates of clause NC-1 are harmless (min
// is idempotent). Also re-zeros the sort counters for the next replay.
__global__ void __launch_bounds__(128, 8)
cnf_k(unsigned int* __restrict__ out) {
    __shared__ uint4 s_m[4][32];

    const int t    = threadIdx.x;
    const int w    = t >> 5;
    const int lane = t & 31;

    // reset histogram/cursors for the next graph replay (safe: scatter done)
    {
        int zi = blockIdx.x * 128 + t;
        if (zi < NV) { g_cnt[zi] = 0u; g_cur[zi] = 0u; }
    }

    const __half2 inf2 = __halves2half2(__ushort_as_half(0x7C00), __ushort_as_half(0x7C00));
    __half2 m0 = inf2, m1 = inf2, m2 = inf2, m3 = inf2;

    const int gw = blockIdx.x * 4 + w;
    int c = gw * CPW;
    const int cmax = NC - 1;

    uint4 qa = __ldg(&g_cl[min(c, cmax)]);
    uint4 qb = __ldg(&g_cl[min(c + 1, cmax)]);

    #pragma unroll 1
    for (int k = 0; k < CPW / 2; ++k) {
        // 6 row gathers: one LDG.128 each (lane-sliced full 512B row)
        uint4 xA0 = __ldg((const uint4*)(g_tab + qa.x) + lane);
        uint4 xA1 = __ldg((const uint4*)(g_tab + qa.y) + lane);
        uint4 xA2 = __ldg((const uint4*)(g_tab + qa.z) + lane);
        uint4 xB0 = __ldg((const uint4*)(g_tab + qb.x) + lane);
        uint4 xB1 = __ldg((const uint4*)(g_tab + qb.y) + lane);
        uint4 xB2 = __ldg((const uint4*)(g_tab + qb.z) + lane);

        // prefetch next pair's clause words while rows are in flight
        c += 2;
        uint4 na, nb;
        if (k + 1 < CPW / 2) {
            na = __ldg(&g_cl[min(c, cmax)]);
            nb = __ldg(&g_cl[min(c + 1, cmax)]);
        }

        __half2 cA0 = __hmax2(__hmax2(h2(xA0.x), h2(xA1.x)), h2(xA2.x));
        __half2 cA1 = __hmax2(__hmax2(h2(xA0.y), h2(xA1.y)), h2(xA2.y));
        __half2 cA2 = __hmax2(__hmax2(h2(xA0.z), h2(xA1.z)), h2(xA2.z));
        __half2 cA3 = __hmax2(__hmax2(h2(xA0.w), h2(xA1.w)), h2(xA2.w));
        __half2 cB0 = __hmax2(__hmax2(h2(xB0.x), h2(xB1.x)), h2(xB2.x));
        __half2 cB1 = __hmax2(__hmax2(h2(xB0.y), h2(xB1.y)), h2(xB2.y));
        __half2 cB2 = __hmax2(__hmax2(h2(xB0.z), h2(xB1.z)), h2(xB2.z));
        __half2 cB3 = __hmax2(__hmax2(h2(xB0.w), h2(xB1.w)), h2(xB2.w));

        m0 = __hmin2(m0, __hmin2(cA0, cB0));
        m1 = __hmin2(m1, __hmin2(cA1, cB1));
        m2 = __hmin2(m2, __hmin2(cA2, cB2));
        m3 = __hmin2(m3, __hmin2(cA3, cB3));

        qa = na; qb = nb;
    }

    uint4 mv;
    mv.x = *reinterpret_cast<unsigned int*>(&m0);
    mv.y = *reinterpret_cast<unsigned int*>(&m1);
    mv.z = *reinterpret_cast<unsigned int*>(&m2);
    mv.w = *reinterpret_cast<unsigned int*>(&m3);
    s_m[w][lane] = mv;
    __syncthreads();

    {
        int l = t >> 2, i = t & 3;
        const unsigned int* c0 = (const unsigned int*)&s_m[0][l];
        const unsigned int* c1 = (const unsigned int*)&s_m[1][l];
        const unsigned int* c2 = (const unsigned int*)&s_m[2][l];
        const unsigned int* c3 = (const unsigned int*)&s_m[3][l];
        __half2 r = __hmin2(__hmin2(h2(c0[i]), h2(c1[i])), __hmin2(h2(c2[i]), h2(c3[i])));
        // uint bit order == float order for non-negative floats
        atomicMin(&out[2 * t + 0], __float_as_uint(__low2float(r)));
        atomicMin(&out[2 * t + 1], __float_as_uint(__high2float(r)));
    }
}

extern "C" void kernel_launch(void* const* d_in, const int* in_sizes, int n_in,
                              void* d_out, int out_size) {
    const float*        input   = (const float*)d_in[0];
    const unsigned int* idx_raw = (const unsigned int*)d_in[1];
    const unsigned int* neg_raw = (const unsigned int*)d_in[2];
    unsigned int*       out     = (unsigned int*)d_out;

    prep_k<<<GRID_PREP, 256>>>(input, idx_raw, out);
    scatter_k<<<GRID_SCAT, 256>>>(idx_raw, neg_raw);
    cnf_k<<<GRID_MAIN, 128>>>(out);
}